// round 3
// baseline (speedup 1.0000x reference)
#include <cuda_runtime.h>
#include <math.h>
#include <stdint.h>
#include <stddef.h>

// Problem constants
// VOCAB=50000, EMB=256, HID=512, K=48, H=256, B=64, T=512
// LSTM scans over the B axis (64 sequential steps), inner batch = T = 512.

#define TT      512      // inner batch of the recurrence (m dimension)
#define NB      64       // number of scan steps (batch)
#define EMBD    256
#define HU      256      // hidden units per direction
#define KTAG    48
#define MTOT    32768    // NB*TT

// ---------------- static device scratch (allocation-free) ----------------
__device__ float g_eT[(size_t)NB * EMBD * TT];          // eT[b][k][t]      32 MB
__device__ float g_WcT[2u * 512u * 1024u];              // WcT[d][k][n']     4 MB
__device__ float g_bc[2 * 1024];                        // bc[d][n']
__device__ float g_hT[2][2 * HU * TT];                  // [parity][d][u][m]
__device__ float g_cT[2 * HU * TT];                     // [d][u][m]
__device__ float g_lstmT[(size_t)512 * MTOT];           // lstmT[d*256+u][b*512+t]  64 MB
__device__ float g_emis[(size_t)MTOT * KTAG];           // emis[b][t][j]     6 MB
__device__ float g_nd[NB];                              // den per batch

__device__ __forceinline__ float sigf(float x) { return 1.0f / (1.0f + __expf(-x)); }

// ---------------- prep: combined transposed gate-reordered weights ----------------
// WcT[d][k][n'], n' = 4*u + gate, source row nsrc = gate*256 + u.
// k < 256 -> Wih[nsrc][k] (input part), k >= 256 -> Whh[nsrc][k-256] (recurrent part).
__global__ void prep_wc(const float* __restrict__ Wih_f, const float* __restrict__ Whh_f,
                        const float* __restrict__ Wih_b, const float* __restrict__ Whh_b) {
    int idx = blockIdx.x * 256 + threadIdx.x;           // 0 .. 2*512*1024-1
    int n  = idx & 1023;
    int k  = (idx >> 10) & 511;
    int d  = idx >> 19;
    int u  = n >> 2, gt = n & 3;
    int nsrc = gt * 256 + u;
    const float* Wih = d ? Wih_b : Wih_f;
    const float* Whh = d ? Whh_b : Whh_f;
    float v = (k < 256) ? Wih[nsrc * 256 + k] : Whh[nsrc * 256 + (k - 256)];
    g_WcT[idx] = v;
}

__global__ void prep_bias(const float* __restrict__ b_f, const float* __restrict__ b_b) {
    int idx = blockIdx.x * 256 + threadIdx.x;           // 0..2047
    int n = idx & 1023;
    int d = idx >> 10;
    int u = n >> 2, gt = n & 3;
    const float* bb = d ? b_b : b_f;
    g_bc[idx] = bb[gt * 256 + u];
}

// ---------------- embedding gather into transposed layout ----------------
// eT[b][k][t] = (x[b][t]==0) ? 0 : emb[x[b][t]][k]
__global__ void gather_embed(const int* __restrict__ x, const float* __restrict__ emb) {
    int id = blockIdx.x * 256 + threadIdx.x;            // 0..32767
    int b = id >> 9;
    int t = id & 511;
    int tok = x[b * TT + t];
    const float4* erow = (const float4*)(emb + (size_t)tok * EMBD);
    float* dst = g_eT + (size_t)b * EMBD * TT + t;
    if (tok == 0) {
        #pragma unroll 4
        for (int k = 0; k < EMBD; k++) dst[(size_t)k * TT] = 0.0f;
    } else {
        #pragma unroll 4
        for (int k4 = 0; k4 < EMBD / 4; k4++) {
            float4 v = __ldg(erow + k4);
            dst[(size_t)(4 * k4 + 0) * TT] = v.x;
            dst[(size_t)(4 * k4 + 1) * TT] = v.y;
            dst[(size_t)(4 * k4 + 2) * TT] = v.z;
            dst[(size_t)(4 * k4 + 3) * TT] = v.w;
        }
    }
}

// ---------------- zero initial h (parity 0) and c ----------------
__global__ void zero_state() {
    int idx = blockIdx.x * 256 + threadIdx.x;
    if (idx < 2 * HU * TT) {
        g_hT[0][idx] = 0.0f;
        g_cT[idx] = 0.0f;
    }
}

// ---------------- fused LSTM step: GEMM (512x1024x512) + elementwise ----------------
// grid (4, 16, 2): bm tiles of 128 m, bn tiles of 64 n', d = direction
#define BM 128
#define BN 64
#define BKK 16

__global__ void __launch_bounds__(256) lstm_step(int s, int parity) {
    int bm = blockIdx.x, bn = blockIdx.y, d = blockIdx.z;
    int b_sel = d ? (NB - 1 - s) : s;

    const float* Ae = g_eT + (size_t)b_sel * EMBD * TT;     // rows k in [0,256)
    const float* Ah = g_hT[parity] + d * (HU * TT);          // rows k in [256,512)
    float* h_out    = g_hT[parity ^ 1] + d * (HU * TT);
    float* cst      = g_cT + d * (HU * TT);
    const float* W  = g_WcT + (size_t)d * 512 * 1024 + bn * 64;

    __shared__ float As[BKK][BM];
    __shared__ float Bs[BKK][BN];

    int tid = threadIdx.x;
    int r = tid >> 4, c = tid & 15;
    int r8 = r * 8, c4 = c * 4;

    int a_kk = tid >> 5;            // 0..7 (plus +8 second row)
    int a_m4 = (tid & 31) * 4;      // 0..124
    int b_kk = tid >> 4;            // 0..15
    int b_n4 = (tid & 15) * 4;

    float acc[8][4];
    #pragma unroll
    for (int i = 0; i < 8; i++)
        #pragma unroll
        for (int j = 0; j < 4; j++) acc[i][j] = 0.0f;

    // staged global->reg->smem double buffering
    float4 ra0, ra1, rb;
    {
        int kg0 = a_kk, kg1 = a_kk + 8;   // kt = 0
        const float* s0 = (kg0 < 256) ? (Ae + (size_t)kg0 * TT) : (Ah + (size_t)(kg0 - 256) * TT);
        const float* s1 = (kg1 < 256) ? (Ae + (size_t)kg1 * TT) : (Ah + (size_t)(kg1 - 256) * TT);
        ra0 = *(const float4*)(s0 + bm * BM + a_m4);
        ra1 = *(const float4*)(s1 + bm * BM + a_m4);
        rb  = *(const float4*)(W + (size_t)b_kk * 1024 + b_n4);
    }

    for (int kt = 0; kt < 32; kt++) {
        *(float4*)&As[a_kk][a_m4]     = ra0;
        *(float4*)&As[a_kk + 8][a_m4] = ra1;
        *(float4*)&Bs[b_kk][b_n4]     = rb;
        __syncthreads();

        if (kt < 31) {
            int kg0 = (kt + 1) * BKK + a_kk;
            int kg1 = kg0 + 8;
            const float* s0 = (kg0 < 256) ? (Ae + (size_t)kg0 * TT) : (Ah + (size_t)(kg0 - 256) * TT);
            const float* s1 = (kg1 < 256) ? (Ae + (size_t)kg1 * TT) : (Ah + (size_t)(kg1 - 256) * TT);
            ra0 = *(const float4*)(s0 + bm * BM + a_m4);
            ra1 = *(const float4*)(s1 + bm * BM + a_m4);
            rb  = *(const float4*)(W + (size_t)((kt + 1) * BKK + b_kk) * 1024 + b_n4);
        }

        #pragma unroll
        for (int kk = 0; kk < BKK; kk++) {
            float4 a0 = *(const float4*)&As[kk][r8];
            float4 a1 = *(const float4*)&As[kk][r8 + 4];
            float4 bv = *(const float4*)&Bs[kk][c4];
            float av[8] = {a0.x, a0.y, a0.z, a0.w, a1.x, a1.y, a1.z, a1.w};
            #pragma unroll
            for (int mi = 0; mi < 8; mi++) {
                acc[mi][0] += av[mi] * bv.x;
                acc[mi][1] += av[mi] * bv.y;
                acc[mi][2] += av[mi] * bv.z;
                acc[mi][3] += av[mi] * bv.w;
            }
        }
        __syncthreads();
    }

    // fused LSTM elementwise epilogue: this thread owns unit u for 8 m-rows
    int u = bn * 16 + c;
    int nb = d * 1024 + u * 4;
    float bi = g_bc[nb + 0], bf = g_bc[nb + 1], bg = g_bc[nb + 2], bo = g_bc[nb + 3];
    int m0 = bm * BM + r8;
    float* crow = cst + (size_t)u * TT;
    float* hrow = h_out + (size_t)u * TT;
    float* lrow = g_lstmT + (size_t)(d * HU + u) * MTOT + (size_t)b_sel * TT;

    #pragma unroll
    for (int mi = 0; mi < 8; mi++) {
        int m = m0 + mi;
        float gi = sigf(acc[mi][0] + bi);
        float gf = sigf(acc[mi][1] + bf);
        float gg = tanhf(acc[mi][2] + bg);
        float go = sigf(acc[mi][3] + bo);
        float cc = gf * crow[m] + gi * gg;
        crow[m] = cc;
        float h = go * tanhf(cc);
        hrow[m] = h;
        lrow[m] = h;
    }
}

// ---------------- emissions: [32768 x 48] = lstmT^T [32768 x 512] @ fc_W^T ----------------
__global__ void __launch_bounds__(256) emissions_kernel(const float* __restrict__ fc_W,
                                                        const float* __restrict__ fc_b) {
    __shared__ float Ws[KTAG][64];
    int tid = threadIdx.x;
    int m = blockIdx.x * 256 + tid;

    float acc[KTAG];
    #pragma unroll
    for (int j = 0; j < KTAG; j++) acc[j] = 0.0f;

    for (int kt = 0; kt < 8; kt++) {          // 8 tiles of 64 k
        __syncthreads();
        #pragma unroll
        for (int i = 0; i < 12; i++) {
            int idx = tid + i * 256;          // 0..3071
            int j = idx >> 6, kk = idx & 63;
            Ws[j][kk] = fc_W[(size_t)j * 512 + kt * 64 + kk];
        }
        __syncthreads();
        #pragma unroll 4
        for (int kk4 = 0; kk4 < 16; kk4++) {
            float a0 = g_lstmT[(size_t)(kt * 64 + kk4 * 4 + 0) * MTOT + m];
            float a1 = g_lstmT[(size_t)(kt * 64 + kk4 * 4 + 1) * MTOT + m];
            float a2 = g_lstmT[(size_t)(kt * 64 + kk4 * 4 + 2) * MTOT + m];
            float a3 = g_lstmT[(size_t)(kt * 64 + kk4 * 4 + 3) * MTOT + m];
            #pragma unroll
            for (int j = 0; j < KTAG; j++) {
                float4 w = *(const float4*)&Ws[j][kk4 * 4];
                acc[j] += a0 * w.x;
                acc[j] += a1 * w.y;
                acc[j] += a2 * w.z;
                acc[j] += a3 * w.w;
            }
        }
    }
    float* out = g_emis + (size_t)m * KTAG;
    #pragma unroll
    for (int j = 0; j < KTAG; j++) out[j] = acc[j] + __ldg(fc_b + j);
}

// ---------------- CRF forward (denominator): 64 blocks, one per batch ----------------
__global__ void __launch_bounds__(KTAG) crf_forward(const float* __restrict__ start_t,
                                                    const float* __restrict__ end_t,
                                                    const float* __restrict__ trans) {
    int b = blockIdx.x;
    int j = threadIdx.x;  // 0..47
    __shared__ float tr[KTAG * KTAG];
    __shared__ float alpha[KTAG];
    __shared__ float red[KTAG];

    for (int idx = j; idx < KTAG * KTAG; idx += KTAG) tr[idx] = trans[idx];
    alpha[j] = start_t[j] + g_emis[(size_t)(b * TT + 0) * KTAG + j];
    __syncthreads();

    for (int t = 1; t < TT; t++) {
        float e = g_emis[(size_t)(b * TT + t) * KTAG + j];
        float v[KTAG];
        float mx = -1e30f;
        #pragma unroll
        for (int i = 0; i < KTAG; i++) {
            v[i] = alpha[i] + tr[i * KTAG + j];
            mx = fmaxf(mx, v[i]);
        }
        float s = 0.0f;
        #pragma unroll
        for (int i = 0; i < KTAG; i++) s += __expf(v[i] - mx);
        float nxt = e + mx + __logf(s);
        __syncthreads();
        alpha[j] = nxt;
        __syncthreads();
    }

    red[j] = alpha[j] + end_t[j];
    __syncthreads();
    if (j == 0) {
        float mx = -1e30f;
        for (int i = 0; i < KTAG; i++) mx = fmaxf(mx, red[i]);
        float s = 0.0f;
        for (int i = 0; i < KTAG; i++) s += __expf(red[i] - mx);
        g_nd[b] = mx + __logf(s);
    }
}

// ---------------- numerator + final reduction ----------------
__global__ void __launch_bounds__(NB) num_final(const int* __restrict__ tags,
                                                const float* __restrict__ start_t,
                                                const float* __restrict__ end_t,
                                                const float* __restrict__ trans,
                                                float* __restrict__ out) {
    int b = threadIdx.x;  // 0..63
    __shared__ float sm[NB];
    const int* tg = tags + b * TT;
    int prev = tg[0];
    float num = start_t[prev] + g_emis[(size_t)(b * TT) * KTAG + prev];
    for (int t = 1; t < TT; t++) {
        int cur = tg[t];
        num += trans[prev * KTAG + cur] + g_emis[(size_t)(b * TT + t) * KTAG + cur];
        prev = cur;
    }
    num += end_t[prev];
    sm[b] = num - g_nd[b];
    __syncthreads();
    if (b == 0) {
        float s = 0.0f;
        for (int i = 0; i < NB; i++) s += sm[i];
        out[0] = -s / (float)NB;
    }
}

// ---------------- launcher ----------------
extern "C" void kernel_launch(void* const* d_in, const int* in_sizes, int n_in,
                              void* d_out, int out_size) {
    const int*   x       = (const int*)d_in[0];
    const int*   tags    = (const int*)d_in[1];
    // d_in[2] = mask (all ones by construction; values do not affect the result)
    const float* emb     = (const float*)d_in[3];
    const float* Wih_f   = (const float*)d_in[4];
    const float* Whh_f   = (const float*)d_in[5];
    const float* b_f     = (const float*)d_in[6];
    const float* Wih_b   = (const float*)d_in[7];
    const float* Whh_b   = (const float*)d_in[8];
    const float* b_b     = (const float*)d_in[9];
    const float* fc_W    = (const float*)d_in[10];
    const float* fc_b    = (const float*)d_in[11];
    const float* start_t = (const float*)d_in[12];
    const float* end_t   = (const float*)d_in[13];
    const float* trans   = (const float*)d_in[14];
    float* out = (float*)d_out;

    prep_wc<<<4096, 256>>>(Wih_f, Whh_f, Wih_b, Whh_b);
    prep_bias<<<8, 256>>>(b_f, b_b);
    gather_embed<<<128, 256>>>(x, emb);
    zero_state<<<(2 * HU * TT + 255) / 256, 256>>>();

    for (int s = 0; s < NB; s++) {
        lstm_step<<<dim3(4, 16, 2), 256>>>(s, s & 1);
    }

    emissions_kernel<<<MTOT / 256, 256>>>(fc_W, fc_b);
    crf_forward<<<NB, KTAG>>>(start_t, end_t, trans);
    num_final<<<1, NB>>>(tags, start_t, end_t, trans, out);
}